// round 3
// baseline (speedup 1.0000x reference)
#include <cuda_runtime.h>

// Problem constants
constexpr int Bb = 64, Tt = 12, Nn = 1370, Cc = 8, Hh = 64;
constexpr int NSEQ = Bb * Nn;           // 87680
constexpr int G    = 4 * Hh;            // 256 gate rows
constexpr int TILE = 64;                // sequences per block (87680 / 64 = 1370 exact)
constexpr int THREADS = 512;            // 8 threads per sequence
constexpr int HP   = 68;                // padded h row stride (floats): 4-way-conflict max, 16B aligned

// Shared memory layout (float offsets)
constexpr int OFF_WHH  = 0;                      // [256][64]
constexpr int OFF_WIH  = OFF_WHH + G * Hh;       // [256][8]
constexpr int OFF_BIAS = OFF_WIH + G * Cc;       // [256] (b_ih + b_hh)
constexpr int OFF_WFC  = OFF_BIAS + G;           // [8][64]
constexpr int OFF_BFC  = OFF_WFC + Cc * Hh;      // [8]
constexpr int OFF_X    = OFF_BFC + 8;            // [64][8]
constexpr int OFF_H    = OFF_X + TILE * Cc;      // [64][68]
constexpr int SMEM_FLOATS = OFF_H + TILE * HP;
constexpr int SMEM_BYTES  = SMEM_FLOATS * 4;     // 96288 B -> 1 block/SM

static_assert(OFF_X % 4 == 0 && OFF_H % 4 == 0, "16B alignment for float4 views");

__device__ __forceinline__ float sigf(float x) {
    return __fdividef(1.0f, 1.0f + __expf(-x));
}
__device__ __forceinline__ float tanhfast(float x) {
    // tanh(x) = 1 - 2/(exp(2x)+1); exact limits at +-inf under __expf/__fdividef
    return 1.0f - __fdividef(2.0f, 1.0f + __expf(2.0f * x));
}

#define XPROJ(ACC, ROW)                                                          \
    {                                                                            \
        const float4 wa = *reinterpret_cast<const float4*>(sWih + (ROW) * Cc);   \
        const float4 wb = *reinterpret_cast<const float4*>(sWih + (ROW) * Cc + 4);\
        ACC = fmaf(wa.x, xa.x, ACC); ACC = fmaf(wa.y, xa.y, ACC);                \
        ACC = fmaf(wa.z, xa.z, ACC); ACC = fmaf(wa.w, xa.w, ACC);                \
        ACC = fmaf(wb.x, xb.x, ACC); ACC = fmaf(wb.y, xb.y, ACC);                \
        ACC = fmaf(wb.z, xb.z, ACC); ACC = fmaf(wb.w, xb.w, ACC);                \
    }

#define HPROJ(ACC, ROW)                                                               \
    {                                                                                 \
        const float4 w4 = *reinterpret_cast<const float4*>(sWhh + (ROW) * Hh + jq * 4);\
        ACC = fmaf(w4.x, h4.x, ACC); ACC = fmaf(w4.y, h4.y, ACC);                     \
        ACC = fmaf(w4.z, h4.z, ACC); ACC = fmaf(w4.w, h4.w, ACC);                     \
    }

__global__ void __launch_bounds__(THREADS, 1)
lstm_fused_kernel(const float* __restrict__ x,
                  const float* __restrict__ W_ih,
                  const float* __restrict__ W_hh,
                  const float* __restrict__ b_ih,
                  const float* __restrict__ b_hh,
                  const float* __restrict__ W_fc,
                  const float* __restrict__ b_fc,
                  float* __restrict__ out)
{
    extern __shared__ float sm[];
    float* sWhh = sm + OFF_WHH;
    float* sWih = sm + OFF_WIH;
    float* sB   = sm + OFF_BIAS;
    float* sWfc = sm + OFF_WFC;
    float* sBfc = sm + OFF_BFC;
    float* sX   = sm + OFF_X;
    float* sH   = sm + OFF_H;

    const int tid = threadIdx.x;

    // ---- Stage weights into shared (once per block) ----
    {
        const float4* g4 = reinterpret_cast<const float4*>(W_hh);
        float4*       s4 = reinterpret_cast<float4*>(sWhh);
        for (int i = tid; i < G * Hh / 4; i += THREADS) s4[i] = g4[i];
    }
    {
        const float4* g4 = reinterpret_cast<const float4*>(W_ih);
        float4*       s4 = reinterpret_cast<float4*>(sWih);
        for (int i = tid; i < G * Cc / 4; i += THREADS) s4[i] = g4[i];
    }
    for (int i = tid; i < G; i += THREADS) sB[i] = b_ih[i] + b_hh[i];
    {
        const float4* g4 = reinterpret_cast<const float4*>(W_fc);
        float4*       s4 = reinterpret_cast<float4*>(sWfc);
        for (int i = tid; i < Cc * Hh / 4; i += THREADS) s4[i] = g4[i];
    }
    if (tid < Cc) sBfc[tid] = b_fc[tid];
    // zero h
    for (int i = tid; i < TILE * HP; i += THREADS) sH[i] = 0.0f;

    // ---- Thread roles ----
    const int w  = tid >> 5;                 // warp 0..15
    const int l  = tid & 31;
    const int s  = l + ((w >> 3) << 5);      // sequence within tile, 0..63
    const int kc = w & 7;                    // k-chunk 0..7 (uniform within warp -> broadcast weight loads)
    const int k0 = kc << 3;

    // x loader mapping: one float per thread per step, fully coalesced
    const int ls  = tid >> 3, lc = tid & 7;
    const int lgs = blockIdx.x * TILE + ls;  // global sequence = b*N + n
    const int lb  = lgs / Nn;
    const int ln  = lgs - lb * Nn;
    const int lx0 = ((lb * Tt) * Nn + ln) * Cc + lc;

    float c_[8], hn[8];
    #pragma unroll
    for (int i = 0; i < 8; i++) c_[i] = 0.0f;

    for (int t = 0; t < Tt; ++t) {
        __syncthreads();                           // prev step's reads of sX/sH done
        sX[ls * Cc + lc] = x[lx0 + t * Nn * Cc];
        __syncthreads();

        float ai[8], af[8], ag[8], ao[8];
        #pragma unroll
        for (int kk = 0; kk < 8; kk++) {
            ai[kk] = sB[k0 + kk];
            af[kk] = sB[64 + k0 + kk];
            ag[kk] = sB[128 + k0 + kk];
            ao[kk] = sB[192 + k0 + kk];
        }

        // input projection (C = 8)
        {
            const float4 xa = *reinterpret_cast<const float4*>(sX + s * Cc);
            const float4 xb = *reinterpret_cast<const float4*>(sX + s * Cc + 4);
            #pragma unroll
            for (int kk = 0; kk < 8; kk++) {
                XPROJ(ai[kk], k0 + kk)
                XPROJ(af[kk], 64 + k0 + kk)
                XPROJ(ag[kk], 128 + k0 + kk)
                XPROJ(ao[kk], 192 + k0 + kk)
            }
        }

        // recurrent projection h @ W_hh^T (H = 64)
        {
            const float* hrow = sH + s * HP;
            #pragma unroll 4
            for (int jq = 0; jq < 16; jq++) {
                const float4 h4 = *reinterpret_cast<const float4*>(hrow + jq * 4);
                #pragma unroll
                for (int kk = 0; kk < 8; kk++) {
                    HPROJ(ai[kk], k0 + kk)
                    HPROJ(af[kk], 64 + k0 + kk)
                    HPROJ(ag[kk], 128 + k0 + kk)
                    HPROJ(ao[kk], 192 + k0 + kk)
                }
            }
        }

        // nonlinearities + cell update (c stays in registers)
        #pragma unroll
        for (int kk = 0; kk < 8; kk++) {
            const float iv = sigf(ai[kk]);
            const float fv = sigf(af[kk]);
            const float gv = tanhfast(ag[kk]);
            const float ov = sigf(ao[kk]);
            const float cv = fmaf(fv, c_[kk], iv * gv);
            c_[kk] = cv;
            hn[kk] = ov * tanhfast(cv);
        }

        __syncthreads();                           // all reads of old h done before overwrite
        #pragma unroll
        for (int kk = 0; kk < 8; kk++) sH[s * HP + k0 + kk] = hn[kk];
    }
    __syncthreads();

    // ---- FC epilogue: y[seq][c] = h . W_fc[c] + b_fc[c] ----
    {
        const int oc = tid & 7, os = tid >> 3;
        const float* hr = sH + os * HP;
        const float* wr = sWfc + oc * Hh;
        float acc = sBfc[oc];
        #pragma unroll 8
        for (int k = 0; k < Hh; k++) acc = fmaf(wr[k], hr[k], acc);
        out[(blockIdx.x * TILE + os) * Cc + oc] = acc;   // (B, N, C) flat, seq-major: coalesced
    }
}

extern "C" void kernel_launch(void* const* d_in, const int* in_sizes, int n_in,
                              void* d_out, int out_size) {
    const float* x    = (const float*)d_in[0];
    const float* W_ih = (const float*)d_in[1];
    const float* W_hh = (const float*)d_in[2];
    const float* b_ih = (const float*)d_in[3];
    const float* b_hh = (const float*)d_in[4];
    const float* W_fc = (const float*)d_in[5];
    const float* b_fc = (const float*)d_in[6];
    float* out = (float*)d_out;

    cudaFuncSetAttribute(lstm_fused_kernel,
                         cudaFuncAttributeMaxDynamicSharedMemorySize, SMEM_BYTES);
    lstm_fused_kernel<<<NSEQ / TILE, THREADS, SMEM_BYTES>>>(
        x, W_ih, W_hh, b_ih, b_hh, W_fc, b_fc, out);
}